// round 1
// baseline (speedup 1.0000x reference)
#include <cuda_runtime.h>
#include <cstdint>

// Problem constants (fixed by the reference)
#define NB     64      // mel bands (k)
#define OC     128     // out channels (o)
#define BATCH  4       // b
#define TLEN   1024    // t
#define FBINS  1025    // stft bins (f)

// GEMM tiling
#define TM     64      // t-tile per block
#define TK     16      // K chunk
#define WMAX   512     // max supported band width (runtime W << this)

// Scratch: folded weights [k][kk][o] with kk = w*2 + c  (size uses runtime KTOT stride)
__device__ float g_fw[NB * 2 * WMAX * OC];
// GEMM-natural output staging: [k][b][t][o]
__device__ float g_scr[NB * BATCH * TLEN * OC];

typedef unsigned long long u64t;

__device__ __forceinline__ u64t pack2(float lo, float hi) {
    u64t r;
    asm("mov.b64 %0, {%1, %2};" : "=l"(r) : "f"(lo), "f"(hi));
    return r;
}
// Packed dual-fp32 FMA (Blackwell FFMA2): d.lo += a.lo*b.lo ; d.hi += a.hi*b.hi
__device__ __forceinline__ void fma2(u64t& d, u64t a, u64t b) {
    asm("fma.rn.f32x2 %0, %1, %2, %0;" : "+l"(d) : "l"(a), "l"(b));
}

// ---------------------------------------------------------------------------
// Kernel 0: fold mel weights into pre_w.
// fw[k][w*2+c][o] = mel_w[k][w] * pre_w[k][c][w][o]
// K-dim order (w outer, c inner) makes c = kk&1, w = kk>>1 cheap in the GEMM.
// ---------------------------------------------------------------------------
__global__ void prep_kernel(const float* __restrict__ mel_w,
                            const float* __restrict__ pre_w, int W) {
    int o  = threadIdx.x;      // 0..127
    int kk = blockIdx.x;       // 0..2W-1
    int k  = blockIdx.y;       // 0..63
    int c = kk & 1, w = kk >> 1;
    int KTOT = 2 * W;
    g_fw[(k * KTOT + kk) * OC + o] =
        mel_w[k * W + w] * pre_w[((k * 2 + c) * W + w) * OC + o];
}

// ---------------------------------------------------------------------------
// Kernel 1: per-band GEMM.
//   C[t, o] = bias[o] + sum_kk A[t, kk] * B[kk, o]
//   A[t, kk] = x[b, c, t0+t, idx[k, w]]   (kk = w*2+c)
//   B        = folded weights g_fw
// Block: 256 threads, tile M=64 (t) x N=128 (o, full), K chunks of 16.
// Each thread: 4 t x 8 o = 32 outputs kept as 16 packed f32x2 accumulators.
// Writes to g_scr[k][b][t][o] (coalesced float4-equivalent stores).
// ---------------------------------------------------------------------------
__global__ __launch_bounds__(256) void gemm_kernel(
    const float* __restrict__ x, const int* __restrict__ idx,
    const float* __restrict__ bias, int W, int KTOT, int nChunks) {
    __shared__ float As[TK][TM];       // [kk][t]
    __shared__ float Bs[TK][OC];       // [kk][o]

    int k  = blockIdx.z;
    int b  = blockIdx.y;
    int t0 = blockIdx.x * TM;
    int tid = threadIdx.x;
    int tx = tid & 15;                 // o group: o0 = tx*8
    int ty = tid >> 4;                 // t group: tbase = ty*4

    // Init accumulators with bias (each (t,o) owned by exactly one thread)
    u64t acc[4][4];
    {
        const float* bp = bias + k * OC + tx * 8;
        float4 bb0 = *(const float4*)(bp);
        float4 bb1 = *(const float4*)(bp + 4);
        u64t i0 = pack2(bb0.x, bb0.y);
        u64t i1 = pack2(bb0.z, bb0.w);
        u64t i2 = pack2(bb1.x, bb1.y);
        u64t i3 = pack2(bb1.z, bb1.w);
#pragma unroll
        for (int ti = 0; ti < 4; ti++) {
            acc[ti][0] = i0; acc[ti][1] = i1; acc[ti][2] = i2; acc[ti][3] = i3;
        }
    }

    const float* xb = x + (size_t)(b * 2) * (TLEN * FBINS);
    const int*   idxk = idx + k * W;
    const float* fwk  = g_fw + (size_t)k * KTOT * OC;

    for (int ch = 0; ch < nChunks; ch++) {
        int kk0 = ch * TK;
        // --- load A tile: 16 kk x 64 t; thread loads 4 consecutive kk for one t
        {
            int tA = tid >> 2;             // 0..63
            int kA = (tid & 3) * 4;        // 0,4,8,12
#pragma unroll
            for (int j = 0; j < 4; j++) {
                int kkg = kk0 + kA + j;
                float v = 0.f;
                if (kkg < KTOT) {
                    int c = kkg & 1, w = kkg >> 1;
                    int f = idxk[w];       // padded taps: f=0, weight=0 -> harmless
                    v = xb[(size_t)(c * TLEN + t0 + tA) * FBINS + f];
                }
                As[kA + j][tA] = v;
            }
        }
        // --- load B tile: 16 kk x 128 o, fully coalesced
        {
#pragma unroll
            for (int i = 0; i < 8; i++) {
                int e = tid + i * 256;
                int kkL = e >> 7, o = e & 127;
                int kkg = kk0 + kkL;
                Bs[kkL][o] = (kkg < KTOT) ? fwk[(size_t)kkg * OC + o] : 0.f;
            }
        }
        __syncthreads();

#pragma unroll
        for (int kkL = 0; kkL < TK; kkL++) {
            float4 av = *(const float4*)&As[kkL][ty * 4];
            ulonglong2 bq0 = *(const ulonglong2*)&Bs[kkL][tx * 8];
            ulonglong2 bq1 = *(const ulonglong2*)&Bs[kkL][tx * 8 + 4];
            u64t bp0 = bq0.x, bp1 = bq0.y, bp2 = bq1.x, bp3 = bq1.y;
            float aa[4] = {av.x, av.y, av.z, av.w};
#pragma unroll
            for (int ti = 0; ti < 4; ti++) {
                u64t ad = pack2(aa[ti], aa[ti]);
                fma2(acc[ti][0], ad, bp0);
                fma2(acc[ti][1], ad, bp1);
                fma2(acc[ti][2], ad, bp2);
                fma2(acc[ti][3], ad, bp3);
            }
        }
        __syncthreads();
    }

    // Epilogue: coalesced 16B stores to GEMM-natural scratch layout
    float* sp = g_scr + ((size_t)(k * BATCH + b) * TLEN + t0 + ty * 4) * OC + tx * 8;
#pragma unroll
    for (int ti = 0; ti < 4; ti++) {
        ulonglong2 v0; v0.x = acc[ti][0]; v0.y = acc[ti][1];
        ulonglong2 v1; v1.x = acc[ti][2]; v1.y = acc[ti][3];
        *(ulonglong2*)(sp + (size_t)ti * OC)     = v0;
        *(ulonglong2*)(sp + (size_t)ti * OC + 4) = v1;
    }
}

// ---------------------------------------------------------------------------
// Kernel 2: transpose (k,b,t,o) -> (b,o,t,k), coalesced both directions via smem.
// One block per (b, t): 64x128 tile in, 128x64 tile out.
// ---------------------------------------------------------------------------
__global__ __launch_bounds__(256) void trans_kernel(float* __restrict__ out) {
    __shared__ float sm[NB][OC + 1];
    int t = blockIdx.x;
    int b = blockIdx.y;
    int tid = threadIdx.x;

    const float* src = g_scr + ((size_t)b * TLEN + t) * OC;  // + k*(BATCH*TLEN*OC)
#pragma unroll
    for (int i = 0; i < 32; i++) {
        int e = tid + i * 256;         // 0..8191
        int kk = e >> 7, o = e & 127;  // coalesced: consecutive tid -> consecutive o
        sm[kk][o] = src[(size_t)kk * (BATCH * TLEN * OC) + o];
    }
    __syncthreads();

    float* dst = out + ((size_t)b * OC) * (TLEN * (size_t)NB) + (size_t)t * NB;
#pragma unroll
    for (int i = 0; i < 32; i++) {
        int e = tid + i * 256;
        int o = e >> 6, kk = e & 63;   // coalesced: consecutive tid -> consecutive k
        dst[(size_t)o * (TLEN * NB) + kk] = sm[kk][o];
    }
}

// ---------------------------------------------------------------------------
extern "C" void kernel_launch(void* const* d_in, const int* in_sizes, int n_in,
                              void* d_out, int out_size) {
    const float* x     = (const float*)d_in[0];
    const int*   idx   = (const int*)  d_in[1];   // jnp demotes int64 -> int32
    const float* mel_w = (const float*)d_in[2];
    const float* pre_w = (const float*)d_in[3];
    const float* pre_b = (const float*)d_in[4];
    float* out = (float*)d_out;

    int W = in_sizes[1] / NB;
    int KTOT = 2 * W;
    int nChunks = (KTOT + TK - 1) / TK;

    dim3 gp(KTOT, NB);
    prep_kernel<<<gp, OC>>>(mel_w, pre_w, W);

    dim3 gg(TLEN / TM, BATCH, NB);
    gemm_kernel<<<gg, 256>>>(x, idx, pre_b, W, KTOT, nChunks);

    dim3 gt(TLEN, BATCH);
    trans_kernel<<<gt, 256>>>(out);
}

// round 4
// speedup vs baseline: 1.8115x; 1.8115x over previous
#include <cuda_runtime.h>
#include <cstdint>

// Problem constants (fixed by the reference)
#define NB     64      // mel bands (k)
#define OC     128     // out channels (o)
#define BATCH  4       // b
#define TLEN   1024    // t
#define FBINS  1025    // stft bins (f)

// GEMM tiling
#define TM     128     // t-tile per block
#define TK     16      // K chunk
#define ASTR   132     // As row stride in floats (TM + 4): STS 2-way max, LDS.128 aligned
#define BSTR   132     // Bs row stride in floats (OC + 4)
#define WCAP   256     // max band width staged in smem

// GEMM-natural output staging: [k][b][t][o]
__device__ float g_scr[NB * BATCH * TLEN * OC];

typedef unsigned long long u64t;

__device__ __forceinline__ u64t pack2(float lo, float hi) {
    u64t r;
    asm("mov.b64 %0, {%1, %2};" : "=l"(r) : "f"(lo), "f"(hi));
    return r;
}
// Packed dual-fp32 FMA (Blackwell FFMA2): d.lo += a.lo*b.lo ; d.hi += a.hi*b.hi
__device__ __forceinline__ void fma2(u64t& d, u64t a, u64t b) {
    asm("fma.rn.f32x2 %0, %1, %2, %0;" : "+l"(d) : "l"(a), "l"(b));
}

// ---------------------------------------------------------------------------
// Per-band GEMM with K order kk = c*W + w (c outer, w inner):
//   - consecutive kk -> consecutive f = idx[w] -> coalesced x loads
//   - B tile is a contiguous slab of pre_w: pre_w[(k*KTOT + kk)*OC + o]
//   - mel folded into A (matches reference multiply order exactly)
// Block: 256 thr, tile M=128(t) x N=128(o) x K=16, double-buffered smem,
// register-prefetched global loads. Thread tile: 8t x (4+4)o.
// ---------------------------------------------------------------------------
__global__ __launch_bounds__(256, 2) void gemm_kernel(
    const float* __restrict__ x, const int* __restrict__ idx,
    const float* __restrict__ mel_w, const float* __restrict__ pre_w,
    const float* __restrict__ bias, int W, int KTOT, int nChunks) {
    __shared__ __align__(16) float As[2][TK][ASTR];
    __shared__ __align__(16) float Bs[2][TK][BSTR];
    __shared__ int   idx_s[WCAP];
    __shared__ float mel_s[WCAP];

    const int k  = blockIdx.z;
    const int b  = blockIdx.y;
    const int t0 = blockIdx.x * TM;
    const int tid = threadIdx.x;
    const int tx = tid & 15;    // o groups: tx*4 and 64+tx*4
    const int ty = tid >> 4;    // t group: ty*8 .. ty*8+7

    // Stage band metadata
    for (int e = tid; e < W; e += 256) {
        idx_s[e] = idx[k * W + e];
        mel_s[e] = mel_w[k * W + e];
    }

    // Init accumulators with bias
    u64t acc[8][4];
    {
        const float* bp = bias + k * OC;
        float4 b0 = *(const float4*)(bp + tx * 4);
        float4 b1 = *(const float4*)(bp + 64 + tx * 4);
        u64t i0 = pack2(b0.x, b0.y), i1 = pack2(b0.z, b0.w);
        u64t i2 = pack2(b1.x, b1.y), i3 = pack2(b1.z, b1.w);
#pragma unroll
        for (int ti = 0; ti < 8; ti++) {
            acc[ti][0] = i0; acc[ti][1] = i1; acc[ti][2] = i2; acc[ti][3] = i3;
        }
    }

    __syncthreads();  // idx_s / mel_s visible

    const float* xb = x + (size_t)b * 2 * TLEN * FBINS;
    const float* pw = pre_w + (size_t)k * KTOT * OC;

    float aR[8], bR[8];

    // ---- global-load helpers (register prefetch) ----
    // A: thread owns fixed kk (=tid&15) in chunk, 8 t rows (coalesced in f across lanes)
    auto loadA = [&](int ch) {
        int kkg = ch * TK + (tid & 15);
        float mel = 0.f; int f = 0; int c = 0;
        if (kkg < KTOT) {
            c = (kkg >= W);
            int w = kkg - (c ? W : 0);
            f = idx_s[w]; mel = mel_s[w];   // padded taps: f=0, mel=0
        }
        const float* ap = xb + ((size_t)(c * TLEN + t0 + (tid >> 4))) * FBINS + f;
#pragma unroll
        for (int i = 0; i < 8; i++)
            aR[i] = ap[(size_t)i * 16 * FBINS] * mel;
    };
    // B: contiguous 512B rows of pre_w, fully coalesced
    auto loadB = [&](int ch) {
        int kbase = ch * TK + (tid >> 7);
        int o = tid & 127;
#pragma unroll
        for (int i = 0; i < 8; i++) {
            int kkg = kbase + 2 * i;
            bR[i] = (kkg < KTOT) ? pw[(size_t)kkg * OC + o] : 0.f;
        }
    };
    auto stsAB = [&](int buf) {
        int kk = tid & 15, tA = tid >> 4;
#pragma unroll
        for (int i = 0; i < 8; i++)
            As[buf][kk][tA + i * 16] = aR[i];
        int kr = tid >> 7, o = tid & 127;
#pragma unroll
        for (int i = 0; i < 8; i++)
            Bs[buf][kr + 2 * i][o] = bR[i];
    };

    loadA(0); loadB(0);

    for (int ch = 0; ch < nChunks; ch++) {
        int buf = ch & 1;
        stsAB(buf);
        __syncthreads();
        if (ch + 1 < nChunks) { loadA(ch + 1); loadB(ch + 1); }

        const float* Ap = &As[buf][0][0] + ty * 8;
        const float* Bp = &Bs[buf][0][0] + tx * 4;
#pragma unroll
        for (int kkL = 0; kkL < TK; kkL++) {
            // B: 2x LDS.128, conflict-free (16B lane stride covers 128B rows)
            ulonglong2 q0 = *(const ulonglong2*)(Bp + kkL * BSTR);
            ulonglong2 q1 = *(const ulonglong2*)(Bp + kkL * BSTR + 64);
            // A: 2x LDS.128 broadcast (2 addresses per warp)
            float4 a0 = *(const float4*)(Ap + kkL * ASTR);
            float4 a1 = *(const float4*)(Ap + kkL * ASTR + 4);
            float av[8] = {a0.x, a0.y, a0.z, a0.w, a1.x, a1.y, a1.z, a1.w};
#pragma unroll
            for (int ti = 0; ti < 8; ti++) {
                u64t ad = pack2(av[ti], av[ti]);
                fma2(acc[ti][0], ad, q0.x);
                fma2(acc[ti][1], ad, q0.y);
                fma2(acc[ti][2], ad, q1.x);
                fma2(acc[ti][3], ad, q1.y);
            }
        }
        __syncthreads();
    }

    // Epilogue: coalesced 16B stores to GEMM-natural staging
    float* sp = g_scr + ((size_t)(k * BATCH + b) * TLEN + t0 + ty * 8) * OC;
#pragma unroll
    for (int ti = 0; ti < 8; ti++) {
        ulonglong2 v0; v0.x = acc[ti][0]; v0.y = acc[ti][1];
        ulonglong2 v1; v1.x = acc[ti][2]; v1.y = acc[ti][3];
        *(ulonglong2*)(sp + (size_t)ti * OC + tx * 4)      = v0;
        *(ulonglong2*)(sp + (size_t)ti * OC + 64 + tx * 4) = v1;
    }
}

// ---------------------------------------------------------------------------
// Transpose (k,b,t,o) -> (b,o,t,k), coalesced both directions via smem.
// ---------------------------------------------------------------------------
__global__ __launch_bounds__(256) void trans_kernel(float* __restrict__ out) {
    __shared__ float sm[NB][OC + 1];
    int t = blockIdx.x;
    int b = blockIdx.y;
    int tid = threadIdx.x;

    const float* src = g_scr + ((size_t)b * TLEN + t) * OC;
#pragma unroll
    for (int i = 0; i < 32; i++) {
        int e = tid + i * 256;
        int kk = e >> 7, o = e & 127;
        sm[kk][o] = src[(size_t)kk * (BATCH * TLEN * OC) + o];
    }
    __syncthreads();

    float* dst = out + ((size_t)b * OC) * (TLEN * (size_t)NB) + (size_t)t * NB;
#pragma unroll
    for (int i = 0; i < 32; i++) {
        int e = tid + i * 256;
        int o = e >> 6, kk = e & 63;
        dst[(size_t)o * (TLEN * NB) + kk] = sm[kk][o];
    }
}

// ---------------------------------------------------------------------------
extern "C" void kernel_launch(void* const* d_in, const int* in_sizes, int n_in,
                              void* d_out, int out_size) {
    const float* x     = (const float*)d_in[0];
    const int*   idx   = (const int*)  d_in[1];
    const float* mel_w = (const float*)d_in[2];
    const float* pre_w = (const float*)d_in[3];
    const float* pre_b = (const float*)d_in[4];
    float* out = (float*)d_out;

    int W = in_sizes[1] / NB;
    int KTOT = 2 * W;
    int nChunks = (KTOT + TK - 1) / TK;

    dim3 gg(TLEN / TM, BATCH, NB);
    gemm_kernel<<<gg, 256>>>(x, idx, mel_w, pre_w, pre_b, W, KTOT, nChunks);

    dim3 gt(TLEN, BATCH);
    trans_kernel<<<gt, 256>>>(out);
}

// round 6
// speedup vs baseline: 2.7594x; 1.5233x over previous
#include <cuda_runtime.h>
#include <cuda_bf16.h>
#include <cstdint>

// Problem constants
#define NB     64
#define OC     128
#define BATCH  4
#define TLEN   1024
#define FBINS  1025
#define TM     128     // t rows per CTA
#define TK     16      // K chunk (one m16n8k16 K-step)
#define WCAP   192

// Smem layout (dynamic): per buffer 4 tiles of 128 rows x 48B (24 bf16, 16 used)
//   AH=0, AL=6144, BH=12288, BL=18432 ; buffer stride 24576
#define BUFSZ  24576
#define T_AH   0
#define T_AL   6144
#define T_BH   12288
#define T_BL   18432
#define SM_IDX 49152           // int[WCAP]
#define SM_MEL (49152+768)     // float[WCAP]
#define SM_BIAS (49152+1536)   // float[128]
#define SM_BYTES 51200
#define RSTR   48              // bytes per tile row

// Device scratch
__device__ float    g_scr[NB * BATCH * TLEN * OC];   // (k,b,t,o)
__device__ unsigned g_bh32[NB * OC * 256];           // B hi bf16x2 [k][o][kkpad/2]
__device__ unsigned g_bl32[NB * OC * 256];           // B lo

typedef unsigned u32;

__device__ __forceinline__ u32 smem_u32(const void* p) {
    u32 a;
    asm("{ .reg .u64 t; cvta.to.shared.u64 t, %1; cvt.u32.u64 %0, t; }" : "=r"(a) : "l"(p));
    return a;
}
__device__ __forceinline__ void cp16(u32 dst, const void* src) {
    asm volatile("cp.async.cg.shared.global [%0], [%1], 16;" :: "r"(dst), "l"(src) : "memory");
}
__device__ __forceinline__ void cp_commit() { asm volatile("cp.async.commit_group;" ::: "memory"); }
__device__ __forceinline__ void cp_wait0()  { asm volatile("cp.async.wait_group 0;" ::: "memory"); }

#define LDX4(r, addr) \
    asm volatile("ldmatrix.sync.aligned.m8n8.x4.shared.b16 {%0,%1,%2,%3}, [%4];" \
        : "=r"((r)[0]), "=r"((r)[1]), "=r"((r)[2]), "=r"((r)[3]) : "r"(addr))

#define MMA(d, A, b0, b1) \
    asm volatile("mma.sync.aligned.m16n8k16.row.col.f32.bf16.bf16.f32 " \
        "{%0,%1,%2,%3}, {%4,%5,%6,%7}, {%8,%9}, {%0,%1,%2,%3};" \
        : "+f"((d)[0]), "+f"((d)[1]), "+f"((d)[2]), "+f"((d)[3]) \
        : "r"((A)[0]), "r"((A)[1]), "r"((A)[2]), "r"((A)[3]), "r"(b0), "r"(b1))

__device__ __forceinline__ unsigned short bf16hi(float v) {
    return __bfloat16_as_ushort(__float2bfloat16_rn(v));
}

// ---------------------------------------------------------------------------
// Prep: transpose + bf16-split pre_w -> g_bh/g_bl [k][o][kkpad], kk = c*W+w.
// ---------------------------------------------------------------------------
__global__ __launch_bounds__(256) void prep_kernel(const float* __restrict__ pre_w,
                                                   int W, int KTOT, int KKPAD) {
    __shared__ float tile[64][129];
    int ch = blockIdx.x, k = blockIdx.y, tid = threadIdx.x;
#pragma unroll
    for (int i = 0; i < 32; i++) {
        int e = tid + i * 256;
        int kkL = e >> 7, o = e & 127;
        int kkg = ch * 64 + kkL;
        float v = 0.f;
        if (kkg < KTOT) {
            int c = (kkg >= W), w = kkg - (c ? W : 0);
            v = pre_w[((size_t)(k * 2 + c) * W + w) * OC + o];
        }
        tile[kkL][o] = v;
    }
    __syncthreads();
#pragma unroll
    for (int i = 0; i < 32; i++) {
        int e = tid + i * 256;
        int o = e >> 6, kkL = e & 63;
        int kkg = ch * 64 + kkL;
        if (kkg < KKPAD) {
            float v = tile[kkL][o];
            unsigned short h = bf16hi(v);
            float fh = __uint_as_float(((u32)h) << 16);
            unsigned short l = bf16hi(v - fh);
            size_t d = (size_t)(k * OC + o) * KKPAD + kkg;
            ((unsigned short*)g_bh32)[d] = h;
            ((unsigned short*)g_bl32)[d] = l;
        }
    }
}

// ---------------------------------------------------------------------------
// Tensor-core band GEMM via mma.sync bf16 3-term split.
// CTA: (k, b, t-tile 128). 8 warps 4(M)x2(N), warp tile 32x64.
// ---------------------------------------------------------------------------
__global__ __launch_bounds__(256, 2) void gemm_mma(
    const float* __restrict__ x, const int* __restrict__ idx,
    const float* __restrict__ mel_w, const float* __restrict__ bias,
    int W, int KTOT, int nChunks, int KKPAD) {
    extern __shared__ char smem[];
    const u32 sb = smem_u32(smem);
    const int tid = threadIdx.x, wid = tid >> 5, lane = tid & 31;
    const int k = blockIdx.z, b = blockIdx.y, t0 = blockIdx.x * TM;
    const int wm = wid >> 1, wn = wid & 1;         // warp grid 4x2
    const int mbase = wm * 32, nbase = wn * 64;

    int*   idx_s  = (int*)(smem + SM_IDX);
    float* mel_s  = (float*)(smem + SM_MEL);
    float* bias_s = (float*)(smem + SM_BIAS);
    for (int e = tid; e < W; e += 256) {
        idx_s[e] = idx[k * W + e];
        mel_s[e] = mel_w[k * W + e];
    }
    if (tid < 128) bias_s[tid] = bias[k * OC + tid];
    __syncthreads();

    const float* xb = x + (size_t)b * 2 * TLEN * FBINS;
    const int kkT = tid & 15;          // this thread's k column within chunk
    const int rbase = tid >> 4;        // rows rbase + 16*i

    // --- A prefetch: 8 gathered+mel-scaled fp32 (coalesced over lanes) ---
    float aR[8];
    auto loadA = [&](int ch) {
        int ke = ch * TK + kkT;
        float mel = 0.f; int f = 0, c = 0;
        if (ke < KTOT) {
            c = (ke >= W);
            int w = ke - (c ? W : 0);
            f = idx_s[w]; mel = mel_s[w];
        }
        const float* ap = xb + (size_t)(c * TLEN + t0 + rbase) * FBINS + f;
#pragma unroll
        for (int i = 0; i < 8; i++)
            aR[i] = ap[(size_t)i * 16 * FBINS] * mel;
    };
    // --- A split + STS into [row][kk] bf16 tiles ---
    auto stsA = [&](u32 off) {
#pragma unroll
        for (int i = 0; i < 8; i++) {
            int r = rbase + 16 * i;
            float a = aR[i];
            unsigned short h = bf16hi(a);
            float fh = __uint_as_float(((u32)h) << 16);
            unsigned short l = bf16hi(a - fh);
            u32 ba = off + (u32)r * RSTR + (u32)kkT * 2;
            *(unsigned short*)(smem + ba + T_AH) = h;
            *(unsigned short*)(smem + ba + T_AL) = l;
        }
    };
    // --- B: cp.async 16B segments from pre-split global (hi+lo, 4KB each) ---
    const int oB = tid >> 1, segB = tid & 1;
    const size_t brow = (size_t)(k * OC + oB) * (KKPAD >> 1);
    auto issueB = [&](int ch, u32 off) {
        const u32* srcH = g_bh32 + brow + ch * 8 + segB * 4;
        const u32* srcL = g_bl32 + brow + ch * 8 + segB * 4;
        u32 dst = sb + off + (u32)oB * RSTR + (u32)segB * 16;
        cp16(dst + T_BH, srcH);
        cp16(dst + T_BL, srcL);
        cp_commit();
    };

    float acc[2][8][4];
#pragma unroll
    for (int mt = 0; mt < 2; mt++)
#pragma unroll
        for (int nt = 0; nt < 8; nt++)
#pragma unroll
            for (int j = 0; j < 4; j++) acc[mt][nt][j] = 0.f;

    issueB(0, 0);
    loadA(0);

    for (int ch = 0; ch < nChunks; ch++) {
        const u32 off = (u32)(ch & 1) * BUFSZ;
        stsA(off);
        cp_wait0();
        __syncthreads();
        if (ch + 1 < nChunks) { issueB(ch + 1, off ^ BUFSZ); loadA(ch + 1); }

        // A fragments (hi/lo, 2 m-tiles)
        u32 ah[2][4], al[2][4];
#pragma unroll
        for (int mt = 0; mt < 2; mt++) {
            u32 aaddr = sb + off + (u32)(mbase + mt * 16 + (lane & 15)) * RSTR
                      + ((u32)(lane >> 4) << 4);
            LDX4(ah[mt], aaddr + T_AH);
            LDX4(al[mt], aaddr + T_AL);
        }
#pragma unroll
        for (int np = 0; np < 4; np++) {
            int rn = nbase + np * 16 + (lane & 7) + ((lane >> 1) & 8);
            u32 baddr = sb + off + (u32)rn * RSTR + (((u32)(lane >> 3) & 1) << 4);
            u32 bh[4], bl[4];
            LDX4(bh, baddr + T_BH);
            LDX4(bl, baddr + T_BL);
#pragma unroll
            for (int h = 0; h < 2; h++) {
                int nt = np * 2 + h;
#pragma unroll
                for (int mt = 0; mt < 2; mt++) {
                    MMA(acc[mt][nt], ah[mt], bh[2 * h], bh[2 * h + 1]);
                    MMA(acc[mt][nt], al[mt], bh[2 * h], bh[2 * h + 1]);
                    MMA(acc[mt][nt], ah[mt], bl[2 * h], bl[2 * h + 1]);
                }
            }
        }
        __syncthreads();
    }

    // Epilogue: bias + store (k,b,t,o). c-frag: rows lane>>2, +8; cols 2*(lane&3).
#pragma unroll
    for (int mt = 0; mt < 2; mt++) {
        int m0 = mbase + mt * 16 + (lane >> 2);
        float* base0 = g_scr + ((size_t)(k * BATCH + b) * TLEN + t0 + m0) * OC;
        float* base1 = base0 + 8 * OC;
#pragma unroll
        for (int nt = 0; nt < 8; nt++) {
            int o0 = nbase + nt * 8 + (lane & 3) * 2;
            float2 bb = *(float2*)(bias_s + o0);
            float2 v0, v1;
            v0.x = acc[mt][nt][0] + bb.x; v0.y = acc[mt][nt][1] + bb.y;
            v1.x = acc[mt][nt][2] + bb.x; v1.y = acc[mt][nt][3] + bb.y;
            *(float2*)(base0 + o0) = v0;
            *(float2*)(base1 + o0) = v1;
        }
    }
}

// ---------------------------------------------------------------------------
// Transpose (k,b,t,o) -> (b,o,t,k) (48.9us, ~56% HBM — unchanged)
// ---------------------------------------------------------------------------
__global__ __launch_bounds__(256) void trans_kernel(float* __restrict__ out) {
    __shared__ float sm[NB][OC + 1];
    int t = blockIdx.x, b = blockIdx.y, tid = threadIdx.x;
    const float* src = g_scr + ((size_t)b * TLEN + t) * OC;
#pragma unroll
    for (int i = 0; i < 32; i++) {
        int e = tid + i * 256;
        int kk = e >> 7, o = e & 127;
        sm[kk][o] = src[(size_t)kk * (BATCH * TLEN * OC) + o];
    }
    __syncthreads();
    float* dst = out + ((size_t)b * OC) * (TLEN * (size_t)NB) + (size_t)t * NB;
#pragma unroll
    for (int i = 0; i < 32; i++) {
        int e = tid + i * 256;
        int o = e >> 6, kk = e & 63;
        dst[(size_t)o * (TLEN * NB) + kk] = sm[kk][o];
    }
}

// ---------------------------------------------------------------------------
extern "C" void kernel_launch(void* const* d_in, const int* in_sizes, int n_in,
                              void* d_out, int out_size) {
    const float* x     = (const float*)d_in[0];
    const int*   idx   = (const int*)  d_in[1];
    const float* mel_w = (const float*)d_in[2];
    const float* pre_w = (const float*)d_in[3];
    const float* pre_b = (const float*)d_in[4];
    float* out = (float*)d_out;

    int W = in_sizes[1] / NB;
    int KTOT = 2 * W;
    int nCh = (KTOT + TK - 1) / TK;       // 16-wide chunks
    int KKPAD = nCh * TK;
    int nCh64 = (KKPAD + 63) / 64;

    cudaFuncSetAttribute(gemm_mma, cudaFuncAttributeMaxDynamicSharedMemorySize, SM_BYTES);

    prep_kernel<<<dim3(nCh64, NB), 256>>>(pre_w, W, KTOT, KKPAD);
    gemm_mma<<<dim3(TLEN / TM, BATCH, NB), 256, SM_BYTES>>>(x, idx, mel_w, pre_b,
                                                            W, KTOT, nCh, KKPAD);
    trans_kernel<<<dim3(TLEN, BATCH), 256>>>(out);
}